// round 1
// baseline (speedup 1.0000x reference)
#include <cuda_runtime.h>

// Problem constants (fixed by the reference)
#define BB 16
#define SS 2048
#define HH 1024

// Scratch for the folded projection vector u2[j] = sum_h v[h] * attn_w[h, H+j]
__device__ float g_u2[HH];

// ---------------------------------------------------------------------------
// Kernel 1: u2 = v^T @ attn_w[:, H:2H]   (1024 outputs, each a 1024-dot)
// warp-per-output-column. Column access is strided (2H floats) but total
// traffic is tiny (4 MB unique).
// ---------------------------------------------------------------------------
__global__ __launch_bounds__(256) void u2_kernel(
    const float* __restrict__ attn_w,  // [H, 2H] row-major
    const float* __restrict__ v)       // [1, H]
{
    const int warp = threadIdx.x >> 5;
    const int lane = threadIdx.x & 31;
    const int j = blockIdx.x * 8 + warp;          // output column 0..1023

    float acc = 0.f;
    const float* col = attn_w + HH + j;           // &attn_w[0, H+j]
#pragma unroll
    for (int it = 0; it < HH / 32; ++it) {
        const int h = it * 32 + lane;
        acc += __ldg(v + h) * __ldg(col + (size_t)h * (2 * HH));
    }
#pragma unroll
    for (int m = 16; m; m >>= 1)
        acc += __shfl_xor_sync(0xffffffffu, acc, m);
    if (lane == 0) g_u2[j] = acc;
}

// ---------------------------------------------------------------------------
// Kernel 2: scores[row] = enc[row, :] . u2   for row in [0, B*S)
// warp-per-row, float4 vectorized; u2 staged into shared once per block.
// This kernel streams the 128 MB encoder tensor — the HBM-bound core.
// ---------------------------------------------------------------------------
__global__ __launch_bounds__(256) void scores_kernel(
    const float* __restrict__ enc,    // [B, S, H]
    float* __restrict__ out)          // [B*S] scores (in d_out)
{
    __shared__ float4 su2[HH / 4];    // 4 KB
    su2[threadIdx.x] = reinterpret_cast<const float4*>(g_u2)[threadIdx.x];
    __syncthreads();

    const int warp = threadIdx.x >> 5;
    const int lane = threadIdx.x & 31;
    const int row  = blockIdx.x * 8 + warp;       // 0 .. B*S-1

    const float4* e = reinterpret_cast<const float4*>(enc) + (size_t)row * (HH / 4);

    float acc = 0.f;
#pragma unroll
    for (int it = 0; it < 8; ++it) {
        const float4 ev = e[it * 32 + lane];
        const float4 uv = su2[it * 32 + lane];
        acc += ev.x * uv.x + ev.y * uv.y + ev.z * uv.z + ev.w * uv.w;
    }
#pragma unroll
    for (int m = 16; m; m >>= 1)
        acc += __shfl_xor_sync(0xffffffffu, acc, m);
    if (lane == 0) out[row] = acc;
}

// ---------------------------------------------------------------------------
// Kernel 3: in-place row softmax over S=2048, one block per batch row.
// 256 threads x 8 elements, values held in registers between passes.
// ---------------------------------------------------------------------------
__global__ __launch_bounds__(256) void softmax_kernel(float* __restrict__ out)
{
    __shared__ float red[8];
    float* row = out + (size_t)blockIdx.x * SS;
    const int tid  = threadIdx.x;
    const int warp = tid >> 5;
    const int lane = tid & 31;

    float x[8];
    float mx = -1e30f;
#pragma unroll
    for (int i = 0; i < 8; ++i) {
        x[i] = row[tid + i * 256];
        mx = fmaxf(mx, x[i]);
    }
#pragma unroll
    for (int m = 16; m; m >>= 1)
        mx = fmaxf(mx, __shfl_xor_sync(0xffffffffu, mx, m));
    if (lane == 0) red[warp] = mx;
    __syncthreads();
    float bmax = red[0];
#pragma unroll
    for (int i = 1; i < 8; ++i) bmax = fmaxf(bmax, red[i]);
    __syncthreads();   // everyone done reading red before reuse

    float s = 0.f;
#pragma unroll
    for (int i = 0; i < 8; ++i) {
        x[i] = __expf(x[i] - bmax);
        s += x[i];
    }
#pragma unroll
    for (int m = 16; m; m >>= 1)
        s += __shfl_xor_sync(0xffffffffu, s, m);
    if (lane == 0) red[warp] = s;
    __syncthreads();
    float tot = 0.f;
#pragma unroll
    for (int i = 0; i < 8; ++i) tot += red[i];
    const float inv = 1.0f / tot;

#pragma unroll
    for (int i = 0; i < 8; ++i)
        row[tid + i * 256] = x[i] * inv;
}

// ---------------------------------------------------------------------------
// Inputs (metadata order): hidden [B,1,H], encoder_outputs [B,S,H],
//                          attn_w [H,2H], attn_b [H], v [1,H]
// hidden and attn_b are provably unused (softmax shift invariance).
// Output: [B,1,S] float32.
// ---------------------------------------------------------------------------
extern "C" void kernel_launch(void* const* d_in, const int* in_sizes, int n_in,
                              void* d_out, int out_size)
{
    const float* enc    = (const float*)d_in[1];
    const float* attn_w = (const float*)d_in[2];
    const float* v      = (const float*)d_in[4];
    float* out = (float*)d_out;

    u2_kernel<<<HH / 8, 256>>>(attn_w, v);
    scores_kernel<<<(BB * SS) / 8, 256>>>(enc, out);
    softmax_kernel<<<BB, 256>>>(out);
}